// round 7
// baseline (speedup 1.0000x reference)
#include <cuda_runtime.h>
#include <cuda_fp16.h>
#include <cstdint>

#define NN 50000
#define NPAD 50176          // 392 * 128
#define DIM 512
#define NCOL 1024
#define BM 128
#define BN 256
#define BK 64               // fp16 per k-chunk = 128 bytes per row
#define CHUNKS 8            // DIM / BK
#define STAGES 3
#define STAGE_BYTES 49152   // A 16KB + B 32KB
#define SMEM_TOTAL (STAGES * STAGE_BYTES)

typedef unsigned long long ull;

// ---------------- static device scratch (no allocation) ----------------
__device__ __align__(16) __half g_Ah[(size_t)NPAD * DIM];    // 51 MB  fp16 A
__device__ __align__(16) __half g_B1p[NCOL * DIM];           // 1 MB  Bh layer1
__device__ __align__(16) __half g_B2p[NCOL * DIM];           // 1 MB  Bh layer2
__device__ __align__(16) __half g_Ch[(size_t)NPAD * NCOL];   // 102 MB  fp16 C
__device__ float g_part[2 * NN];

// ---------------- PTX helpers ----------------
__device__ __forceinline__ uint32_t smem_u32(const void* p) {
    uint32_t a;
    asm("{ .reg .u64 t; cvta.to.shared.u64 t, %1; cvt.u32.u64 %0, t; }" : "=r"(a) : "l"(p));
    return a;
}
#define CP16(dst, src) asm volatile("cp.async.cg.shared.global [%0], [%1], 16;" :: "r"(dst), "l"(src))
#define CP_COMMIT()    asm volatile("cp.async.commit_group;" ::: "memory")
#define CP_WAIT(n)     asm volatile("cp.async.wait_group %0;" :: "n"(n) : "memory")

#define LDSM_X4(r0, r1, r2, r3, a) \
    asm volatile("ldmatrix.sync.aligned.m8n8.x4.shared.b16 {%0,%1,%2,%3}, [%4];" \
        : "=r"(r0), "=r"(r1), "=r"(r2), "=r"(r3) : "r"(a))

#define MMA16816(c, a, b) \
    asm volatile("mma.sync.aligned.m16n8k16.row.col.f32.f16.f16.f32 " \
        "{%0,%1,%2,%3}, {%4,%5,%6,%7}, {%8,%9}, {%0,%1,%2,%3};" \
        : "+f"((c)[0]), "+f"((c)[1]), "+f"((c)[2]), "+f"((c)[3]) \
        : "r"((a)[0]), "r"((a)[1]), "r"((a)[2]), "r"((a)[3]), "r"((b)[0]), "r"((b)[1]))

// ---------------- weight pack: Bh[n][k], fp16 ----------------
__global__ void packw_kernel(const float* __restrict__ W1, const float* __restrict__ W2) {
    int idx = blockIdx.x * blockDim.x + threadIdx.x;
    if (idx >= NCOL * DIM) return;
    int n = idx >> 9, k = idx & 511;
    int src = (n < DIM) ? (n * NCOL + k) : ((n - DIM) * NCOL + DIM + k);
    g_B1p[idx] = __float2half_rn(W1[src]);
    g_B2p[idx] = __float2half_rn(W2[src]);
}

// ---------------- convert x -> fp16 ----------------
__global__ void convert_x_kernel(const float* __restrict__ x) {
    int i = blockIdx.x;
    int j = threadIdx.x * 4;                       // 128 threads cover 512
    __half* row = g_Ah + (size_t)i * DIM;
    if (i >= NN) { *(ull*)(row + j) = 0ull; return; }
    float4 v4 = *(const float4*)(x + (size_t)i * DIM + j);
    __half h[4] = { __float2half_rn(v4.x), __float2half_rn(v4.y),
                    __float2half_rn(v4.z), __float2half_rn(v4.w) };
    *(ull*)(row + j) = *(ull*)h;
}

// ---------------- fp16 HMMA GEMM: g_Ch[M,1024] = A[M,512] @ B^T ----------------
// CTA 128x256x64, warp tile 64x64 (8 warps 2m x 4n), 3-stage cp.async pipeline.
__global__ __launch_bounds__(256, 1) void gemm_kernel(int layer) {
    extern __shared__ __align__(1024) char smem[];
    const uint32_t sbase = smem_u32(smem);
    const int tid = threadIdx.x;
    const int wid = tid >> 5;
    const int lane = tid & 31;
    const int wm = wid & 1;           // 2 warps along M
    const int wn = wid >> 1;          // 4 warps along N (64 cols each)
    const __half* __restrict__ Bp = layer ? g_B2p : g_B1p;
    const size_t mBase = (size_t)blockIdx.y * BM;
    const int nBase = blockIdx.x * BN;

    const char* gA0 = (const char*)g_Ah + mBase * (DIM * 2);
    const char* gB0 = (const char*)Bp + (size_t)nBase * (DIM * 2);

    auto load_chunk = [&](int kc, int s) {
        uint32_t sA = sbase + s * STAGE_BYTES;
        uint32_t sB = sA + 16384;
        const char* gA = gA0 + kc * 128;
        const char* gB = gB0 + kc * 128;
        #pragma unroll
        for (int i = 0; i < 4; i++) {              // A: 128 rows x 128B
            int u = tid + i * 256;                 // 0..1023
            int r = u >> 3, c = u & 7;
            uint32_t sw = (uint32_t)(r * 128 + (((c ^ (r & 7))) << 4));
            CP16(sA + sw, gA + (size_t)r * 1024 + c * 16);
        }
        #pragma unroll
        for (int i = 0; i < 8; i++) {              // B: 256 rows x 128B
            int u = tid + i * 256;                 // 0..2047
            int r = u >> 3, c = u & 7;
            uint32_t sw = (uint32_t)(r * 128 + (((c ^ (r & 7))) << 4));
            CP16(sB + sw, gB + (size_t)r * 1024 + c * 16);
        }
    };

    float acc[4][8][4];
    #pragma unroll
    for (int i = 0; i < 4; i++)
        #pragma unroll
        for (int j = 0; j < 8; j++)
            #pragma unroll
            for (int q = 0; q < 4; q++) acc[i][j][q] = 0.f;

    load_chunk(0, 0); CP_COMMIT();
    load_chunk(1, 1); CP_COMMIT();

    const int lrow = lane & 15;       // row within 16
    const int lhalf = lane >> 4;      // k-half

    for (int kc = 0; kc < CHUNKS; kc++) {
        CP_WAIT(1);                   // chunk kc resident
        __syncthreads();

        uint32_t sA = sbase + (kc % STAGES) * STAGE_BYTES;
        uint32_t sB = sA + 16384;

        #pragma unroll
        for (int ks = 0; ks < 4; ks++) {
            uint32_t af[4][4], bf[8][2];
            #pragma unroll
            for (int am = 0; am < 4; am++) {
                int row = wm * 64 + am * 16 + lrow;
                int grp = ks * 2 + lhalf;
                uint32_t addr = sA + row * 128 + (((grp ^ (row & 7))) << 4);
                LDSM_X4(af[am][0], af[am][1], af[am][2], af[am][3], addr);
            }
            #pragma unroll
            for (int p = 0; p < 4; p++) {
                int row = wn * 64 + p * 16 + lrow;
                int grp = ks * 2 + lhalf;
                uint32_t addr = sB + row * 128 + (((grp ^ (row & 7))) << 4);
                uint32_t r0, r1, r2, r3;
                LDSM_X4(r0, r1, r2, r3, addr);
                bf[p * 2 + 0][0] = r0; bf[p * 2 + 0][1] = r2;
                bf[p * 2 + 1][0] = r1; bf[p * 2 + 1][1] = r3;
            }
            #pragma unroll
            for (int am = 0; am < 4; am++)
                #pragma unroll
                for (int bn = 0; bn < 8; bn++)
                    MMA16816(acc[am][bn], af[am], bf[bn]);
        }
        if (kc + 2 < CHUNKS) load_chunk(kc + 2, (kc + 2) % STAGES);
        CP_COMMIT();
    }

    // epilogue: fp16 store. c frag m16n8 -> (row = l>>2 [+8], col = (l&3)*2)
    const int crow = lane >> 2;
    const int ccol = (lane & 3) * 2;
    #pragma unroll
    for (int am = 0; am < 4; am++) {
        size_t r0 = mBase + wm * 64 + am * 16 + crow;
        #pragma unroll
        for (int bn = 0; bn < 8; bn++) {
            int c0 = nBase + wn * 64 + bn * 8 + ccol;
            __half2* p0 = (__half2*)(g_Ch + r0 * NCOL + c0);
            __half2* p1 = (__half2*)(g_Ch + (r0 + 8) * NCOL + c0);
            *p0 = __floats2half2_rn(acc[am][bn][0], acc[am][bn][1]);
            *p1 = __floats2half2_rn(acc[am][bn][2], acc[am][bn][3]);
        }
    }
}

// ---------------- layer-1 combine -> fp16: A <- relu(Y + 0.5*(Z0+Z1)) ----------------
__device__ __forceinline__ float2 h2f(uint32_t u) { return __half22float2(*(__half2*)&u); }

__global__ void combine1_kernel(const int* __restrict__ neighs) {
    int i = blockIdx.x;
    int j = threadIdx.x * 4;                       // 4 halves per thread
    __half* row = g_Ah + (size_t)i * DIM;
    if (i >= NN) { *(ull*)(row + j) = 0ull; return; }
    int n0 = neighs[2 * i], n1 = neighs[2 * i + 1];
    uint2 ys = *(const uint2*)(g_Ch + (size_t)i  * NCOL + j);
    uint2 z0 = *(const uint2*)(g_Ch + (size_t)n0 * NCOL + DIM + j);
    uint2 z1 = *(const uint2*)(g_Ch + (size_t)n1 * NCOL + DIM + j);
    float2 sa = h2f(ys.x), sb = h2f(ys.y);
    float2 a0 = h2f(z0.x), b0 = h2f(z0.y);
    float2 a1 = h2f(z1.x), b1 = h2f(z1.y);
    __half h[4];
    h[0] = __float2half_rn(fmaxf(fmaf(0.5f, a0.x + a1.x, sa.x), 0.f));
    h[1] = __float2half_rn(fmaxf(fmaf(0.5f, a0.y + a1.y, sa.y), 0.f));
    h[2] = __float2half_rn(fmaxf(fmaf(0.5f, b0.x + b1.x, sb.x), 0.f));
    h[3] = __float2half_rn(fmaxf(fmaf(0.5f, b0.y + b1.y, sb.y), 0.f));
    *(ull*)(row + j) = *(ull*)h;
}

// ---------------- layer-2 combine fused with FC-head partial dots ----------------
__global__ void combine2_kernel(const int* __restrict__ neighs,
                                const float* __restrict__ fcw,
                                float* __restrict__ out) {
    int i = blockIdx.x;
    int tid = threadIdx.x;
    int j = tid * 4;
    int n0 = neighs[2 * i], n1 = neighs[2 * i + 1];
    uint2 ys = *(const uint2*)(g_Ch + (size_t)i  * NCOL + j);
    uint2 z0 = *(const uint2*)(g_Ch + (size_t)n0 * NCOL + DIM + j);
    uint2 z1 = *(const uint2*)(g_Ch + (size_t)n1 * NCOL + DIM + j);
    float2 sa = h2f(ys.x), sb = h2f(ys.y);
    float2 a0 = h2f(z0.x), b0 = h2f(z0.y);
    float2 a1 = h2f(z1.x), b1 = h2f(z1.y);
    float4 o;
    o.x = fmaxf(fmaf(0.5f, a0.x + a1.x, sa.x), 0.f);
    o.y = fmaxf(fmaf(0.5f, a0.y + a1.y, sa.y), 0.f);
    o.z = fmaxf(fmaf(0.5f, b0.x + b1.x, sb.x), 0.f);
    o.w = fmaxf(fmaf(0.5f, b0.y + b1.y, sb.y), 0.f);
    size_t idx = (size_t)i * DIM + j;
    *(float4*)(out + idx) = o;

    float4 w0 = *(const float4*)(fcw + idx);
    float4 w1 = *(const float4*)(fcw + (size_t)NN * DIM + idx);
    float p0 = o.x * w0.x + o.y * w0.y + o.z * w0.z + o.w * w0.w;
    float p1 = o.x * w1.x + o.y * w1.y + o.z * w1.z + o.w * w1.w;

    __shared__ float s0[128], s1[128];
    s0[tid] = p0; s1[tid] = p1;
    __syncthreads();
    #pragma unroll
    for (int st = 64; st > 0; st >>= 1) {
        if (tid < st) { s0[tid] += s0[tid + st]; s1[tid] += s1[tid + st]; }
        __syncthreads();
    }
    if (tid == 0) { g_part[i] = s0[0]; g_part[NN + i] = s1[0]; }
}

// ---------------- final: deterministic reduce + bias + log_softmax ----------------
__global__ void final_kernel(const float* __restrict__ fcb, float* __restrict__ out2) {
    __shared__ float s0[256], s1[256];
    int tid = threadIdx.x;
    float a = 0.f, b = 0.f;
    for (int i = tid; i < NN; i += 256) { a += g_part[i]; b += g_part[NN + i]; }
    s0[tid] = a; s1[tid] = b;
    __syncthreads();
    #pragma unroll
    for (int st = 128; st > 0; st >>= 1) {
        if (tid < st) { s0[tid] += s0[tid + st]; s1[tid] += s1[tid + st]; }
        __syncthreads();
    }
    if (tid == 0) {
        float l0 = s0[0] + fcb[0];
        float l1 = s1[0] + fcb[1];
        float m = fmaxf(l0, l1);
        float lse = m + logf(expf(l0 - m) + expf(l1 - m));
        out2[0] = l0 - lse;
        out2[1] = l1 - lse;
    }
}

// ---------------- launch ----------------
extern "C" void kernel_launch(void* const* d_in, const int* in_sizes, int n_in,
                              void* d_out, int out_size) {
    const float* x   = (const float*)d_in[0];
    const int*   nb1 = (const int*)  d_in[1];
    const int*   nb2 = (const int*)  d_in[2];
    const float* W1  = (const float*)d_in[3];
    const float* W2  = (const float*)d_in[4];
    const float* fcw = (const float*)d_in[5];
    const float* fcb = (const float*)d_in[6];
    float* out = (float*)d_out;

    cudaFuncSetAttribute(gemm_kernel, cudaFuncAttributeMaxDynamicSharedMemorySize, SMEM_TOTAL);

    packw_kernel<<<(NCOL * DIM + 255) / 256, 256>>>(W1, W2);
    convert_x_kernel<<<NPAD, 128>>>(x);

    dim3 grid(NCOL / BN, NPAD / BM);                       // (4, 392)
    gemm_kernel<<<grid, 256, SMEM_TOTAL>>>(0);             // layer 1 -> g_Ch
    combine1_kernel<<<NPAD, 128>>>(nb1);                   // -> g_Ah (fp16)
    gemm_kernel<<<grid, 256, SMEM_TOTAL>>>(1);             // layer 2 -> g_Ch
    combine2_kernel<<<NN, 128>>>(nb2, fcw, out);           // flat -> d_out, FC partials
    final_kernel<<<1, 256>>>(fcb, out + (size_t)(out_size - 2));
}

// round 8
// speedup vs baseline: 1.1210x; 1.1210x over previous
#include <cuda_runtime.h>
#include <cuda_fp16.h>
#include <cstdint>

#define NN 50000
#define NPAD 50176          // 392 * 128
#define DIM 512
#define NCOL 1024
#define BM 128
#define BN 128
#define BK 64               // fp16 per k-chunk = 128 bytes per row
#define CHUNKS 8            // DIM / BK
#define STAGES 3
#define STAGE_BYTES 32768   // A 16KB + B 16KB
#define SMEM_TOTAL (STAGES * STAGE_BYTES)

typedef unsigned long long ull;

// ---------------- static device scratch (no allocation) ----------------
__device__ __align__(16) __half g_Ah[(size_t)NPAD * DIM];    // 51 MB  fp16 A
__device__ __align__(16) __half g_B1p[NCOL * DIM];           // 1 MB  Bh layer1
__device__ __align__(16) __half g_B2p[NCOL * DIM];           // 1 MB  Bh layer2
__device__ __align__(16) __half g_Ch[(size_t)NPAD * NCOL];   // 102 MB  fp16 C
__device__ float g_part[2 * NN];

// ---------------- PTX helpers ----------------
__device__ __forceinline__ uint32_t smem_u32(const void* p) {
    uint32_t a;
    asm("{ .reg .u64 t; cvta.to.shared.u64 t, %1; cvt.u32.u64 %0, t; }" : "=r"(a) : "l"(p));
    return a;
}
#define CP16(dst, src) asm volatile("cp.async.cg.shared.global [%0], [%1], 16;" :: "r"(dst), "l"(src))
#define CP_COMMIT()    asm volatile("cp.async.commit_group;" ::: "memory")
#define CP_WAIT(n)     asm volatile("cp.async.wait_group %0;" :: "n"(n) : "memory")

#define LDSM_X4(r0, r1, r2, r3, a) \
    asm volatile("ldmatrix.sync.aligned.m8n8.x4.shared.b16 {%0,%1,%2,%3}, [%4];" \
        : "=r"(r0), "=r"(r1), "=r"(r2), "=r"(r3) : "r"(a))

#define MMA16816(c, a, b) \
    asm volatile("mma.sync.aligned.m16n8k16.row.col.f32.f16.f16.f32 " \
        "{%0,%1,%2,%3}, {%4,%5,%6,%7}, {%8,%9}, {%0,%1,%2,%3};" \
        : "+f"((c)[0]), "+f"((c)[1]), "+f"((c)[2]), "+f"((c)[3]) \
        : "r"((a)[0]), "r"((a)[1]), "r"((a)[2]), "r"((a)[3]), "r"((b)[0]), "r"((b)[1]))

// ---------------- weight pack: Bh[n][k], fp16 ----------------
__global__ void packw_kernel(const float* __restrict__ W1, const float* __restrict__ W2) {
    int idx = blockIdx.x * blockDim.x + threadIdx.x;
    if (idx >= NCOL * DIM) return;
    int n = idx >> 9, k = idx & 511;
    int src = (n < DIM) ? (n * NCOL + k) : ((n - DIM) * NCOL + DIM + k);
    g_B1p[idx] = __float2half_rn(W1[src]);
    g_B2p[idx] = __float2half_rn(W2[src]);
}

// ---------------- convert x -> fp16 ----------------
__global__ void convert_x_kernel(const float* __restrict__ x) {
    int i = blockIdx.x;
    int j = threadIdx.x * 4;                       // 128 threads cover 512
    __half* row = g_Ah + (size_t)i * DIM;
    if (i >= NN) { *(ull*)(row + j) = 0ull; return; }
    float4 v4 = *(const float4*)(x + (size_t)i * DIM + j);
    __half h[4] = { __float2half_rn(v4.x), __float2half_rn(v4.y),
                    __float2half_rn(v4.z), __float2half_rn(v4.w) };
    *(ull*)(row + j) = *(ull*)h;
}

// ---------------- fp16 HMMA GEMM: g_Ch[M,1024] = A[M,512] @ B^T ----------------
// CTA 128x128x64, warp tile 64x32, 3-stage cp.async pipeline, 2 CTAs/SM.
__global__ __launch_bounds__(256, 2) void gemm_kernel(int layer) {
    extern __shared__ __align__(1024) char smem[];
    const uint32_t sbase = smem_u32(smem);
    const int tid = threadIdx.x;
    const int wid = tid >> 5;
    const int lane = tid & 31;
    const int wm = wid & 1;           // 2 warps along M
    const int wn = wid >> 1;          // 4 warps along N
    const __half* __restrict__ Bp = layer ? g_B2p : g_B1p;
    const size_t mBase = (size_t)blockIdx.y * BM;
    const int nBase = blockIdx.x * BN;

    const char* gA0 = (const char*)g_Ah + mBase * (DIM * 2);
    const char* gB0 = (const char*)Bp + (size_t)nBase * (DIM * 2);

    auto load_chunk = [&](int kc, int s) {
        uint32_t sA = sbase + s * STAGE_BYTES;
        uint32_t sB = sA + 16384;
        const char* gA = gA0 + kc * 128;
        const char* gB = gB0 + kc * 128;
        #pragma unroll
        for (int i = 0; i < 4; i++) {
            int u = tid + i * 256;            // 0..1023
            int r = u >> 3, c = u & 7;
            uint32_t sw = (uint32_t)(r * 128 + (((c ^ (r & 7))) << 4));
            CP16(sA + sw, gA + (size_t)r * 1024 + c * 16);
            CP16(sB + sw, gB + (size_t)r * 1024 + c * 16);
        }
    };

    float acc[4][4][4];
    #pragma unroll
    for (int i = 0; i < 4; i++)
        #pragma unroll
        for (int j = 0; j < 4; j++)
            #pragma unroll
            for (int q = 0; q < 4; q++) acc[i][j][q] = 0.f;

    load_chunk(0, 0); CP_COMMIT();
    load_chunk(1, 1); CP_COMMIT();

    const int lrow = lane & 15;       // row within 16
    const int lhalf = lane >> 4;      // k-half

    for (int kc = 0; kc < CHUNKS; kc++) {
        CP_WAIT(1);                   // chunk kc resident
        __syncthreads();

        uint32_t sA = sbase + (kc % STAGES) * STAGE_BYTES;
        uint32_t sB = sA + 16384;

        #pragma unroll
        for (int ks = 0; ks < 4; ks++) {
            uint32_t af[4][4], bf[4][2];
            #pragma unroll
            for (int am = 0; am < 4; am++) {
                int row = wm * 64 + am * 16 + lrow;
                int grp = ks * 2 + lhalf;
                uint32_t addr = sA + row * 128 + (((grp ^ (row & 7))) << 4);
                LDSM_X4(af[am][0], af[am][1], af[am][2], af[am][3], addr);
            }
            #pragma unroll
            for (int p = 0; p < 2; p++) {
                int row = wn * 32 + p * 16 + lrow;
                int grp = ks * 2 + lhalf;
                uint32_t addr = sB + row * 128 + (((grp ^ (row & 7))) << 4);
                uint32_t r0, r1, r2, r3;
                LDSM_X4(r0, r1, r2, r3, addr);
                bf[p * 2 + 0][0] = r0; bf[p * 2 + 0][1] = r2;
                bf[p * 2 + 1][0] = r1; bf[p * 2 + 1][1] = r3;
            }
            #pragma unroll
            for (int am = 0; am < 4; am++)
                #pragma unroll
                for (int bn = 0; bn < 4; bn++)
                    MMA16816(acc[am][bn], af[am], bf[bn]);
        }
        if (kc + 2 < CHUNKS) load_chunk(kc + 2, (kc + 2) % STAGES);
        CP_COMMIT();
    }

    // epilogue: fp16 store. c frag m16n8 -> (row = l>>2 [+8], col = (l&3)*2)
    const int crow = lane >> 2;
    const int ccol = (lane & 3) * 2;
    #pragma unroll
    for (int am = 0; am < 4; am++) {
        size_t r0 = mBase + wm * 64 + am * 16 + crow;
        #pragma unroll
        for (int bn = 0; bn < 4; bn++) {
            int c0 = nBase + wn * 32 + bn * 8 + ccol;
            __half2* p0 = (__half2*)(g_Ch + r0 * NCOL + c0);
            __half2* p1 = (__half2*)(g_Ch + (r0 + 8) * NCOL + c0);
            *p0 = __floats2half2_rn(acc[am][bn][0], acc[am][bn][1]);
            *p1 = __floats2half2_rn(acc[am][bn][2], acc[am][bn][3]);
        }
    }
}

// ---------------- layer-1 combine -> fp16: A <- relu(Y + 0.5*(Z0+Z1)) ----------------
__device__ __forceinline__ float2 h2f(uint32_t u) { return __half22float2(*(__half2*)&u); }

// 64 threads per row; each thread handles 8 halves via 16B loads.
__global__ void combine1_kernel(const int* __restrict__ neighs) {
    int i = blockIdx.x;
    int j = threadIdx.x * 8;
    __half* row = g_Ah + (size_t)i * DIM;
    if (i >= NN) { *(uint4*)(row + j) = make_uint4(0, 0, 0, 0); return; }
    int n0 = neighs[2 * i], n1 = neighs[2 * i + 1];
    uint4 ys = *(const uint4*)(g_Ch + (size_t)i  * NCOL + j);
    uint4 z0 = *(const uint4*)(g_Ch + (size_t)n0 * NCOL + DIM + j);
    uint4 z1 = *(const uint4*)(g_Ch + (size_t)n1 * NCOL + DIM + j);
    const uint32_t* yp = &ys.x;
    const uint32_t* p0 = &z0.x;
    const uint32_t* p1 = &z1.x;
    __half h[8];
    #pragma unroll
    for (int q = 0; q < 4; q++) {
        float2 s = h2f(yp[q]), a0 = h2f(p0[q]), a1 = h2f(p1[q]);
        h[q * 2 + 0] = __float2half_rn(fmaxf(fmaf(0.5f, a0.x + a1.x, s.x), 0.f));
        h[q * 2 + 1] = __float2half_rn(fmaxf(fmaf(0.5f, a0.y + a1.y, s.y), 0.f));
    }
    *(uint4*)(row + j) = *(uint4*)h;
}

// ---------------- layer-2 combine fused with FC-head partial dots ----------------
// 64 threads per row; each thread handles 8 halves / 8 out floats.
__global__ void combine2_kernel(const int* __restrict__ neighs,
                                const float* __restrict__ fcw,
                                float* __restrict__ out) {
    int i = blockIdx.x;
    int tid = threadIdx.x;
    int j = tid * 8;
    int n0 = neighs[2 * i], n1 = neighs[2 * i + 1];
    uint4 ys = *(const uint4*)(g_Ch + (size_t)i  * NCOL + j);
    uint4 z0 = *(const uint4*)(g_Ch + (size_t)n0 * NCOL + DIM + j);
    uint4 z1 = *(const uint4*)(g_Ch + (size_t)n1 * NCOL + DIM + j);
    const uint32_t* yp = &ys.x;
    const uint32_t* p0 = &z0.x;
    const uint32_t* p1 = &z1.x;
    size_t idx = (size_t)i * DIM + j;
    float o[8];
    #pragma unroll
    for (int q = 0; q < 4; q++) {
        float2 s = h2f(yp[q]), a0 = h2f(p0[q]), a1 = h2f(p1[q]);
        o[q * 2 + 0] = fmaxf(fmaf(0.5f, a0.x + a1.x, s.x), 0.f);
        o[q * 2 + 1] = fmaxf(fmaf(0.5f, a0.y + a1.y, s.y), 0.f);
    }
    *(float4*)(out + idx) = make_float4(o[0], o[1], o[2], o[3]);
    *(float4*)(out + idx + 4) = make_float4(o[4], o[5], o[6], o[7]);

    float p0s = 0.f, p1s = 0.f;
    #pragma unroll
    for (int half = 0; half < 2; half++) {
        float4 w0 = *(const float4*)(fcw + idx + half * 4);
        float4 w1 = *(const float4*)(fcw + (size_t)NN * DIM + idx + half * 4);
        const float* ov = o + half * 4;
        p0s += ov[0] * w0.x + ov[1] * w0.y + ov[2] * w0.z + ov[3] * w0.w;
        p1s += ov[0] * w1.x + ov[1] * w1.y + ov[2] * w1.z + ov[3] * w1.w;
    }

    __shared__ float s0[64], s1[64];
    s0[tid] = p0s; s1[tid] = p1s;
    __syncthreads();
    #pragma unroll
    for (int st = 32; st > 0; st >>= 1) {
        if (tid < st) { s0[tid] += s0[tid + st]; s1[tid] += s1[tid + st]; }
        __syncthreads();
    }
    if (tid == 0) { g_part[i] = s0[0]; g_part[NN + i] = s1[0]; }
}

// ---------------- final: deterministic reduce + bias + log_softmax ----------------
__global__ void final_kernel(const float* __restrict__ fcb, float* __restrict__ out2) {
    __shared__ float s0[256], s1[256];
    int tid = threadIdx.x;
    float a = 0.f, b = 0.f;
    for (int i = tid; i < NN; i += 256) { a += g_part[i]; b += g_part[NN + i]; }
    s0[tid] = a; s1[tid] = b;
    __syncthreads();
    #pragma unroll
    for (int st = 128; st > 0; st >>= 1) {
        if (tid < st) { s0[tid] += s0[tid + st]; s1[tid] += s1[tid + st]; }
        __syncthreads();
    }
    if (tid == 0) {
        float l0 = s0[0] + fcb[0];
        float l1 = s1[0] + fcb[1];
        float m = fmaxf(l0, l1);
        float lse = m + logf(expf(l0 - m) + expf(l1 - m));
        out2[0] = l0 - lse;
        out2[1] = l1 - lse;
    }
}

// ---------------- launch ----------------
extern "C" void kernel_launch(void* const* d_in, const int* in_sizes, int n_in,
                              void* d_out, int out_size) {
    const float* x   = (const float*)d_in[0];
    const int*   nb1 = (const int*)  d_in[1];
    const int*   nb2 = (const int*)  d_in[2];
    const float* W1  = (const float*)d_in[3];
    const float* W2  = (const float*)d_in[4];
    const float* fcw = (const float*)d_in[5];
    const float* fcb = (const float*)d_in[6];
    float* out = (float*)d_out;

    cudaFuncSetAttribute(gemm_kernel, cudaFuncAttributeMaxDynamicSharedMemorySize, SMEM_TOTAL);

    packw_kernel<<<(NCOL * DIM + 255) / 256, 256>>>(W1, W2);
    convert_x_kernel<<<NPAD, 128>>>(x);

    dim3 grid(NCOL / BN, NPAD / BM);                       // (8, 392)
    gemm_kernel<<<grid, 256, SMEM_TOTAL>>>(0);             // layer 1 -> g_Ch
    combine1_kernel<<<NPAD, 64>>>(nb1);                    // -> g_Ah (fp16)
    gemm_kernel<<<grid, 256, SMEM_TOTAL>>>(1);             // layer 2 -> g_Ch
    combine2_kernel<<<NN, 64>>>(nb2, fcw, out);            // flat -> d_out, FC partials
    final_kernel<<<1, 256>>>(fcb, out + (size_t)(out_size - 2));
}